// round 3
// baseline (speedup 1.0000x reference)
#include <cuda_runtime.h>

#define TPB 128
// per-sample smem strides (odd => bank-conflict-free for per-thread access)
#define ESTR 49   // 48 euler floats padded to 49
#define BSTR 17   // 16 lengths padded to 17
#define OSTR 51   // 51 output floats (already odd)

__device__ __forceinline__ void euler_R(float ax, float ay, float az, float R[9]) {
    float sx, cx, sy, cy, sz, cz;
    __sincosf(ax, &sx, &cx);
    __sincosf(ay, &sy, &cy);
    __sincosf(az, &sz, &cz);
    float sxsy = sx * sy;
    float cxsy = cx * sy;
    R[0] = cy * cz;                 R[1] = -cy * sz;                R[2] = sy;
    R[3] = fmaf(sxsy, cz, cx * sz); R[4] = fmaf(-sxsy, sz, cx * cz); R[5] = -sx * cy;
    R[6] = fmaf(-cxsy, cz, sx * sz);R[7] = fmaf(cxsy, sz, sx * cz);  R[8] = cx * cy;
}

__device__ __forceinline__ void compose(const float Mp[9], const float R[9], float Mc[9]) {
#pragma unroll
    for (int i = 0; i < 3; i++) {
#pragma unroll
        for (int j = 0; j < 3; j++) {
            Mc[i * 3 + j] = fmaf(Mp[i * 3 + 0], R[0 + j],
                            fmaf(Mp[i * 3 + 1], R[3 + j],
                                 Mp[i * 3 + 2] * R[6 + j]));
        }
    }
}

extern "C" __global__ void __launch_bounds__(TPB)
fk_kernel(const float* __restrict__ euler, const float* __restrict__ blen,
          float* __restrict__ out, int N)
{
    extern __shared__ float sm[];
    float* s_e = sm;                      // TPB * ESTR
    float* s_b = s_e + TPB * ESTR;        // TPB * BSTR
    float* s_o = s_b + TPB * BSTR;        // TPB * OSTR

    const int t    = threadIdx.x;
    const int base = blockIdx.x * TPB;
    const int ns   = min(TPB, N - base);

    // ---- coalesced load: euler (ns*48 floats = ns*12 float4) ----
    {
        const float4* ge = (const float4*)(euler + (size_t)base * 48);
        const int ne4 = ns * 12;
        for (int i = t; i < ne4; i += TPB) {
            float4 v = ge[i];
            int s = i / 12, r = i - s * 12;
            float* p = s_e + s * ESTR + r * 4;
            p[0] = v.x; p[1] = v.y; p[2] = v.z; p[3] = v.w;
        }
    }
    // ---- coalesced load: bone lengths (ns*16 floats = ns*4 float4) ----
    {
        const float4* gb = (const float4*)(blen + (size_t)base * 16);
        const int nb4 = ns * 4;
        for (int i = t; i < nb4; i += TPB) {
            float4 v = gb[i];
            int s = i >> 2, r = i & 3;
            float* p = s_b + s * BSTR + r * 4;
            p[0] = v.x; p[1] = v.y; p[2] = v.z; p[3] = v.w;
        }
    }
    __syncthreads();

    // ---- per-sample forward kinematics ----
    if (t < ns) {
        const float* e = s_e + t * ESTR;
        const float* L = s_b + t * BSTR;
        float* o = s_o + t * OSTR;

        o[0] = 0.f; o[1] = 0.f; o[2] = 0.f;           // root joint

        float R[9], MA[9], MB[9], M8[9];
        float px, py, pz, p8x, p8y, p8z;

        // ---- leg 1: bones 0,1,2 -> joints 1,2,3 (parent=root, M=I) ----
        euler_R(e[0], e[1], e[2], MA);
        px = L[0] * MA[6]; py = L[0] * MA[7]; pz = L[0] * MA[8];
        o[3] = px; o[4] = py; o[5] = pz;
        euler_R(e[3], e[4], e[5], R);  compose(MA, R, MB);
        px = fmaf(L[1], MB[6], px); py = fmaf(L[1], MB[7], py); pz = fmaf(L[1], MB[8], pz);
        o[6] = px; o[7] = py; o[8] = pz;
        euler_R(e[6], e[7], e[8], R);  compose(MB, R, MA);
        px = fmaf(L[2], MA[6], px); py = fmaf(L[2], MA[7], py); pz = fmaf(L[2], MA[8], pz);
        o[9] = px; o[10] = py; o[11] = pz;

        // ---- leg 2: bones 3,4,5 -> joints 4,5,6 ----
        euler_R(e[9], e[10], e[11], MA);
        px = L[3] * MA[6]; py = L[3] * MA[7]; pz = L[3] * MA[8];
        o[12] = px; o[13] = py; o[14] = pz;
        euler_R(e[12], e[13], e[14], R); compose(MA, R, MB);
        px = fmaf(L[4], MB[6], px); py = fmaf(L[4], MB[7], py); pz = fmaf(L[4], MB[8], pz);
        o[15] = px; o[16] = py; o[17] = pz;
        euler_R(e[15], e[16], e[17], R); compose(MB, R, MA);
        px = fmaf(L[5], MA[6], px); py = fmaf(L[5], MA[7], py); pz = fmaf(L[5], MA[8], pz);
        o[18] = px; o[19] = py; o[20] = pz;

        // ---- spine: bone 6 (0->7), bone 7 (7->8) ----
        euler_R(e[18], e[19], e[20], MA);
        px = L[6] * MA[6]; py = L[6] * MA[7]; pz = L[6] * MA[8];
        o[21] = px; o[22] = py; o[23] = pz;
        euler_R(e[21], e[22], e[23], R); compose(MA, R, M8);
        p8x = fmaf(L[7], M8[6], px); p8y = fmaf(L[7], M8[7], py); p8z = fmaf(L[7], M8[8], pz);
        o[24] = p8x; o[25] = p8y; o[26] = p8z;

        // ---- head: bones 8 (8->9), 9 (9->10) -> joints 9,10 ----
        euler_R(e[24], e[25], e[26], R); compose(M8, R, MA);
        px = fmaf(L[8], MA[6], p8x); py = fmaf(L[8], MA[7], p8y); pz = fmaf(L[8], MA[8], p8z);
        o[27] = px; o[28] = py; o[29] = pz;
        euler_R(e[27], e[28], e[29], R); compose(MA, R, MB);
        px = fmaf(L[9], MB[6], px); py = fmaf(L[9], MB[7], py); pz = fmaf(L[9], MB[8], pz);
        o[30] = px; o[31] = py; o[32] = pz;

        // ---- arm A: bones 10,11,12 (8->11->12->13) -> joints 11,12,13 ----
        euler_R(e[30], e[31], e[32], R); compose(M8, R, MA);
        px = fmaf(L[10], MA[6], p8x); py = fmaf(L[10], MA[7], p8y); pz = fmaf(L[10], MA[8], p8z);
        o[33] = px; o[34] = py; o[35] = pz;
        euler_R(e[33], e[34], e[35], R); compose(MA, R, MB);
        px = fmaf(L[11], MB[6], px); py = fmaf(L[11], MB[7], py); pz = fmaf(L[11], MB[8], pz);
        o[36] = px; o[37] = py; o[38] = pz;
        euler_R(e[36], e[37], e[38], R); compose(MB, R, MA);
        px = fmaf(L[12], MA[6], px); py = fmaf(L[12], MA[7], py); pz = fmaf(L[12], MA[8], pz);
        o[39] = px; o[40] = py; o[41] = pz;

        // ---- arm B: bones 13,14,15 (8->14->15->16) -> joints 14,15,16 ----
        euler_R(e[39], e[40], e[41], R); compose(M8, R, MA);
        px = fmaf(L[13], MA[6], p8x); py = fmaf(L[13], MA[7], p8y); pz = fmaf(L[13], MA[8], p8z);
        o[42] = px; o[43] = py; o[44] = pz;
        euler_R(e[42], e[43], e[44], R); compose(MA, R, MB);
        px = fmaf(L[14], MB[6], px); py = fmaf(L[14], MB[7], py); pz = fmaf(L[14], MB[8], pz);
        o[45] = px; o[46] = py; o[47] = pz;
        euler_R(e[45], e[46], e[47], R); compose(MB, R, MA);
        px = fmaf(L[15], MA[6], px); py = fmaf(L[15], MA[7], py); pz = fmaf(L[15], MA[8], pz);
        o[48] = px; o[49] = py; o[50] = pz;
    }
    __syncthreads();

    // ---- coalesced store: ns*51 floats (ns*51 % 4 == 0 for ns in {128, 32}) ----
    {
        float* go = out + (size_t)base * 51;
        const int nf = ns * 51;
        const int n4 = nf >> 2;
        for (int i = t; i < n4; i += TPB) {
            int g = 4 * i;
            int s0 = g / 51;         int r0 = g - s0 * 51;
            int s1 = (g + 1) / 51;   int r1 = (g + 1) - s1 * 51;
            int s2 = (g + 2) / 51;   int r2 = (g + 2) - s2 * 51;
            int s3 = (g + 3) / 51;   int r3 = (g + 3) - s3 * 51;
            float4 v;
            v.x = s_o[s0 * OSTR + r0];
            v.y = s_o[s1 * OSTR + r1];
            v.z = s_o[s2 * OSTR + r2];
            v.w = s_o[s3 * OSTR + r3];
            ((float4*)go)[i] = v;
        }
        const int rem = nf & 3;      // safety for arbitrary N
        if (rem && t < rem) {
            int g = (n4 << 2) + t;
            int s = g / 51, r = g - s * 51;
            go[g] = s_o[s * OSTR + r];
        }
    }
}

extern "C" void kernel_launch(void* const* d_in, const int* in_sizes, int n_in,
                              void* d_out, int out_size)
{
    const float* euler = (const float*)d_in[0];   // (N,16,3) f32
    const float* blen  = (const float*)d_in[1];   // (N,16,1) f32
    float* out = (float*)d_out;                   // (N,17,3) f32

    const int N = in_sizes[0] / 48;
    const int grid = (N + TPB - 1) / TPB;
    const size_t smem = (size_t)TPB * (ESTR + BSTR + OSTR) * sizeof(float); // 59,904 B

    cudaFuncSetAttribute(fk_kernel, cudaFuncAttributeMaxDynamicSharedMemorySize, (int)smem);
    fk_kernel<<<grid, TPB, smem>>>(euler, blen, out, N);
}

// round 4
// speedup vs baseline: 1.1978x; 1.1978x over previous
#include <cuda_runtime.h>

#define TPB 128
// per-sample smem strides (odd => bank-conflict-free for per-thread access)
#define EOSTR 51  // shared euler-in / output buffer: e[0..47] consumed sequentially,
                  // o[j..j+2] overwrites slots j-3..j-1; root o[0..2] -> slots 48..50
#define BSTR 17   // 16 lengths padded to 17

__device__ __forceinline__ void euler_R(float ax, float ay, float az, float R[9]) {
    float sx, cx, sy, cy, sz, cz;
    __sincosf(ax, &sx, &cx);
    __sincosf(ay, &sy, &cy);
    __sincosf(az, &sz, &cz);
    float sxsy = sx * sy;
    float cxsy = cx * sy;
    R[0] = cy * cz;                 R[1] = -cy * sz;                 R[2] = sy;
    R[3] = fmaf(sxsy, cz, cx * sz); R[4] = fmaf(-sxsy, sz, cx * cz); R[5] = -sx * cy;
    R[6] = fmaf(-cxsy, cz, sx * sz);R[7] = fmaf(cxsy, sz, sx * cz);  R[8] = cx * cy;
}

__device__ __forceinline__ void compose(const float Mp[9], const float R[9], float Mc[9]) {
#pragma unroll
    for (int i = 0; i < 3; i++) {
#pragma unroll
        for (int j = 0; j < 3; j++) {
            Mc[i * 3 + j] = fmaf(Mp[i * 3 + 0], R[0 + j],
                            fmaf(Mp[i * 3 + 1], R[3 + j],
                                 Mp[i * 3 + 2] * R[6 + j]));
        }
    }
}

// write joint position: output float indices j..j+2 (j multiple of 3, j>=3)
// into slots j-3..j-1 of the shared euler/output buffer.
__device__ __forceinline__ void put3(float* o, int j, float x, float y, float z) {
    o[j - 3] = x; o[j - 2] = y; o[j - 1] = z;
}

extern "C" __global__ void __launch_bounds__(TPB)
fk_kernel(const float* __restrict__ euler, const float* __restrict__ blen,
          float* __restrict__ out, int N)
{
    extern __shared__ float sm[];
    float* s_eo = sm;                      // TPB * EOSTR (euler in, positions out)
    float* s_b  = s_eo + TPB * EOSTR;      // TPB * BSTR

    const int t    = threadIdx.x;
    const int base = blockIdx.x * TPB;
    const int ns   = min(TPB, N - base);

    // ---- coalesced load: euler (ns*48 floats = ns*12 float4) ----
    {
        const float4* ge = (const float4*)(euler + (size_t)base * 48);
        const int ne4 = ns * 12;
        for (int i = t; i < ne4; i += TPB) {
            float4 v = ge[i];
            int s = i / 12, r = i - s * 12;
            float* p = s_eo + s * EOSTR + r * 4;
            p[0] = v.x; p[1] = v.y; p[2] = v.z; p[3] = v.w;
        }
    }
    // ---- coalesced load: bone lengths (ns*16 floats = ns*4 float4) ----
    {
        const float4* gb = (const float4*)(blen + (size_t)base * 16);
        const int nb4 = ns * 4;
        for (int i = t; i < nb4; i += TPB) {
            float4 v = gb[i];
            int s = i >> 2, r = i & 3;
            float* p = s_b + s * BSTR + r * 4;
            p[0] = v.x; p[1] = v.y; p[2] = v.z; p[3] = v.w;
        }
    }
    __syncthreads();

    // ---- per-sample forward kinematics (in-place: o[j] -> slot j-3) ----
    if (t < ns) {
        float* eo = s_eo + t * EOSTR;
        const float* L = s_b + t * BSTR;

        // root joint o[0..2] -> slots 48..50 (never touched by euler data)
        eo[48] = 0.f; eo[49] = 0.f; eo[50] = 0.f;

        float R[9], MA[9], MB[9], M8[9];
        float px, py, pz, p8x, p8y, p8z;

        // ---- leg 1: bones 0,1,2 -> joints 1,2,3 (parent=root, M=I) ----
        euler_R(eo[0], eo[1], eo[2], MA);
        px = L[0] * MA[6]; py = L[0] * MA[7]; pz = L[0] * MA[8];
        put3(eo, 3, px, py, pz);
        euler_R(eo[3], eo[4], eo[5], R);  compose(MA, R, MB);
        px = fmaf(L[1], MB[6], px); py = fmaf(L[1], MB[7], py); pz = fmaf(L[1], MB[8], pz);
        put3(eo, 6, px, py, pz);
        euler_R(eo[6], eo[7], eo[8], R);  compose(MB, R, MA);
        px = fmaf(L[2], MA[6], px); py = fmaf(L[2], MA[7], py); pz = fmaf(L[2], MA[8], pz);
        put3(eo, 9, px, py, pz);

        // ---- leg 2: bones 3,4,5 -> joints 4,5,6 ----
        euler_R(eo[9], eo[10], eo[11], MA);
        px = L[3] * MA[6]; py = L[3] * MA[7]; pz = L[3] * MA[8];
        put3(eo, 12, px, py, pz);
        euler_R(eo[12], eo[13], eo[14], R); compose(MA, R, MB);
        px = fmaf(L[4], MB[6], px); py = fmaf(L[4], MB[7], py); pz = fmaf(L[4], MB[8], pz);
        put3(eo, 15, px, py, pz);
        euler_R(eo[15], eo[16], eo[17], R); compose(MB, R, MA);
        px = fmaf(L[5], MA[6], px); py = fmaf(L[5], MA[7], py); pz = fmaf(L[5], MA[8], pz);
        put3(eo, 18, px, py, pz);

        // ---- spine: bone 6 (0->7), bone 7 (7->8) ----
        euler_R(eo[18], eo[19], eo[20], MA);
        px = L[6] * MA[6]; py = L[6] * MA[7]; pz = L[6] * MA[8];
        put3(eo, 21, px, py, pz);
        euler_R(eo[21], eo[22], eo[23], R); compose(MA, R, M8);
        p8x = fmaf(L[7], M8[6], px); p8y = fmaf(L[7], M8[7], py); p8z = fmaf(L[7], M8[8], pz);
        put3(eo, 24, p8x, p8y, p8z);

        // ---- head: bones 8 (8->9), 9 (9->10) -> joints 9,10 ----
        euler_R(eo[24], eo[25], eo[26], R); compose(M8, R, MA);
        px = fmaf(L[8], MA[6], p8x); py = fmaf(L[8], MA[7], p8y); pz = fmaf(L[8], MA[8], p8z);
        put3(eo, 27, px, py, pz);
        euler_R(eo[27], eo[28], eo[29], R); compose(MA, R, MB);
        px = fmaf(L[9], MB[6], px); py = fmaf(L[9], MB[7], py); pz = fmaf(L[9], MB[8], pz);
        put3(eo, 30, px, py, pz);

        // ---- arm A: bones 10,11,12 (8->11->12->13) -> joints 11,12,13 ----
        euler_R(eo[30], eo[31], eo[32], R); compose(M8, R, MA);
        px = fmaf(L[10], MA[6], p8x); py = fmaf(L[10], MA[7], p8y); pz = fmaf(L[10], MA[8], p8z);
        put3(eo, 33, px, py, pz);
        euler_R(eo[33], eo[34], eo[35], R); compose(MA, R, MB);
        px = fmaf(L[11], MB[6], px); py = fmaf(L[11], MB[7], py); pz = fmaf(L[11], MB[8], pz);
        put3(eo, 36, px, py, pz);
        euler_R(eo[36], eo[37], eo[38], R); compose(MB, R, MA);
        px = fmaf(L[12], MA[6], px); py = fmaf(L[12], MA[7], py); pz = fmaf(L[12], MA[8], pz);
        put3(eo, 39, px, py, pz);

        // ---- arm B: bones 13,14,15 (8->14->15->16) -> joints 14,15,16 ----
        euler_R(eo[39], eo[40], eo[41], R); compose(M8, R, MA);
        px = fmaf(L[13], MA[6], p8x); py = fmaf(L[13], MA[7], p8y); pz = fmaf(L[13], MA[8], p8z);
        put3(eo, 42, px, py, pz);
        euler_R(eo[42], eo[43], eo[44], R); compose(MA, R, MB);
        px = fmaf(L[14], MB[6], px); py = fmaf(L[14], MB[7], py); pz = fmaf(L[14], MB[8], pz);
        put3(eo, 45, px, py, pz);
        euler_R(eo[45], eo[46], eo[47], R); compose(MB, R, MA);
        px = fmaf(L[15], MA[6], px); py = fmaf(L[15], MA[7], py); pz = fmaf(L[15], MA[8], pz);
        put3(eo, 48, px, py, pz);   // o[48..50] -> slots 45..47
    }
    __syncthreads();

    // ---- coalesced store: ns*51 floats; output float j lives at slot
    //      (j%51 >= 3 ? j%51-3 : j%51+48) within its sample's stride-51 row ----
    {
        float* go = out + (size_t)base * 51;
        const int nf = ns * 51;
        const int n4 = nf >> 2;
        for (int i = t; i < n4; i += TPB) {
            int g = 4 * i;
            float4 v;
#pragma unroll
            for (int k = 0; k < 4; k++) {
                int gk = g + k;
                int s = gk / 51, r = gk - s * 51;
                int slot = (r >= 3) ? (r - 3) : (r + 48);
                ((float*)&v)[k] = s_eo[s * EOSTR + slot];
            }
            ((float4*)go)[i] = v;
        }
        const int rem = nf & 3;      // safety for arbitrary N
        if (rem && t < rem) {
            int g = (n4 << 2) + t;
            int s = g / 51, r = g - s * 51;
            int slot = (r >= 3) ? (r - 3) : (r + 48);
            go[g] = s_eo[s * EOSTR + slot];
        }
    }
}

extern "C" void kernel_launch(void* const* d_in, const int* in_sizes, int n_in,
                              void* d_out, int out_size)
{
    const float* euler = (const float*)d_in[0];   // (N,16,3) f32
    const float* blen  = (const float*)d_in[1];   // (N,16,1) f32
    float* out = (float*)d_out;                   // (N,17,3) f32

    const int N = in_sizes[0] / 48;
    const int grid = (N + TPB - 1) / TPB;
    const size_t smem = (size_t)TPB * (EOSTR + BSTR) * sizeof(float); // 34,816 B

    cudaFuncSetAttribute(fk_kernel, cudaFuncAttributeMaxDynamicSharedMemorySize, (int)smem);
    cudaFuncSetAttribute(fk_kernel, cudaFuncAttributePreferredSharedMemoryCarveout,
                         cudaSharedmemCarveoutMaxShared);
    fk_kernel<<<grid, TPB, smem>>>(euler, blen, out, N);
}